// round 3
// baseline (speedup 1.0000x reference)
#include <cuda_runtime.h>
#include <math.h>

#define NB      148              // one block per SM, single wave
#define NTHR    320              // 10 warps -> 204 regs/thread, no spills
#define GPB     (NTHR / 8)       // 40 groups per block
#define NGROUPS (NB * GPB)       // 5920
#define NWARP   (NTHR / 32)      // 10

typedef unsigned long long ull;

// Per-block softmax partials: [block][head][ m, s, acc[64] ]
__device__ float g_part[NB][4][66];

// ---- packed f32x2 helpers (ptxas never auto-fuses FFMA2) --------------------
__device__ __forceinline__ ull pk2(float lo, float hi) {
    ull r; asm("mov.b64 %0,{%1,%2};" : "=l"(r) : "f"(lo), "f"(hi)); return r;
}
__device__ __forceinline__ void upk2(float& lo, float& hi, ull p) {
    asm("mov.b64 {%0,%1},%2;" : "=f"(lo), "=f"(hi) : "l"(p));
}
__device__ __forceinline__ ull fma2(ull a, ull b, ull c) {
    ull d; asm("fma.rn.f32x2 %0,%1,%2,%3;" : "=l"(d) : "l"(a), "l"(b), "l"(c)); return d;
}
__device__ __forceinline__ ull mul2(ull a, ull b) {
    ull d; asm("mul.rn.f32x2 %0,%1,%2;" : "=l"(d) : "l"(a), "l"(b)); return d;
}
__device__ __forceinline__ float tanh_ap(float x) {
    float y; asm("tanh.approx.f32 %0,%1;" : "=f"(y) : "f"(x)); return y;
}
// silu(x) = x*sigmoid(x) = h + h*tanh(h), h = x/2  -> 1 MUFU
__device__ __forceinline__ ull silu2(ull xpk, ull halfpk) {
    ull hpk = mul2(xpk, halfpk);
    float h0, h1; upk2(h0, h1, hpk);
    ull tpk = pk2(tanh_ap(h0), tanh_ap(h1));
    return fma2(hpk, tpk, hpk);
}

// -----------------------------------------------------------------------------
// Fused kernel: inline prep (fold q,Wk,W2 -> u,c) + streaming online-softmax.
// 8 lanes per point, TWO points per group per iteration for ILP.
// -----------------------------------------------------------------------------
__global__ void __launch_bounds__(NTHR, 1)
main_kernel(const float* __restrict__ rr,
            const float* __restrict__ ri,
            const float* __restrict__ W1,
            const float* __restrict__ b1,
            const float* __restrict__ W2,
            const float* __restrict__ b2,
            const float* __restrict__ query,
            const float* __restrict__ ipw,   // in_proj_w (192,64)
            const float* __restrict__ ipb,   // in_proj_b (192)
            int N)
{
    __shared__ float qv[64];
    __shared__ float tt[4][64];
    __shared__ float sh_u[4][64];
    __shared__ float sh_c[4];
    __shared__ float sh_m[NWARP][4];
    __shared__ float sh_s[NWARP][4];
    __shared__ float sh_acc[NWARP][4][64];

    const int tid  = threadIdx.x;
    const int lane = tid & 31;
    const int sub  = tid & 7;
    const unsigned gmask = 0xFFu << (lane & 24);

    // ---- inline prep (every block redundantly; ~25K FMA, L2-resident) ------
    if (tid < 64) {
        float a = ipb[tid], a2 = 0.f;
        #pragma unroll 8
        for (int m = 0; m < 64; m += 2) {
            a  = fmaf(query[m],     ipw[tid * 64 + m],     a);
            a2 = fmaf(query[m + 1], ipw[tid * 64 + m + 1], a2);
        }
        qv[tid] = a + a2;
    }
    __syncthreads();
    if (tid < 256) {
        const int h = tid >> 6, j = tid & 63;
        float t = 0.f;
        #pragma unroll 8
        for (int d = 0; d < 16; d++)
            t = fmaf(qv[h * 16 + d], ipw[(64 + h * 16 + d) * 64 + j], t);
        tt[h][j] = t;
    }
    __syncthreads();
    if (tid < 256) {
        const int h = tid >> 6, j = tid & 63;
        float u = 0.f, u2 = 0.f;
        #pragma unroll 8
        for (int jj = 0; jj < 64; jj += 2) {
            u  = fmaf(tt[h][jj],     W2[jj * 64 + j],       u);
            u2 = fmaf(tt[h][jj + 1], W2[(jj + 1) * 64 + j], u2);
        }
        sh_u[h][j] = 0.25f * (u + u2);       // fold 1/sqrt(hd)=0.25
    } else if (tid < 260) {
        const int h = tid - 256;
        float c = 0.f;
        for (int d = 0; d < 16; d++) c = fmaf(qv[h * 16 + d], ipb[64 + h * 16 + d], c);
        for (int jj = 0; jj < 64; jj++) c = fmaf(tt[h][jj], b2[jj], c);
        sh_c[h] = 0.25f * c;
    }
    __syncthreads();

    // ---- per-lane packed constants -----------------------------------------
    const int j0 = sub * 8;
    ull w1ap[4], w1bp[4], b1p[4], u4p[4][4];
    #pragma unroll
    for (int k = 0; k < 4; k++) {
        const int j = j0 + 2 * k;
        w1ap[k] = pk2(W1[2 * j],     W1[2 * j + 2]);
        w1bp[k] = pk2(W1[2 * j + 1], W1[2 * j + 3]);
        b1p[k]  = pk2(b1[j], b1[j + 1]);
        #pragma unroll
        for (int h = 0; h < 4; h++) u4p[h][k] = pk2(sh_u[h][j], sh_u[h][j + 1]);
    }
    float c4[4];
    #pragma unroll
    for (int h = 0; h < 4; h++) c4[h] = sh_c[h];
    const ull halfpk = pk2(0.5f, 0.5f);

    // ---- online softmax state ----------------------------------------------
    float m4[4], s4[4];
    ull accp[4][4];
    #pragma unroll
    for (int h = 0; h < 4; h++) {
        m4[h] = -1e30f; s4[h] = 0.f;
        #pragma unroll
        for (int k = 0; k < 4; k++) accp[h][k] = 0ull;
    }

    // hidden+score partial for one point (r,im), packed over this lane's 8 dims
    #define HIDSCORE(r, im, hid, sc)                                           \
    {                                                                          \
        const ull rpk_ = pk2((r), (r));                                        \
        const ull ipk_ = pk2((im), (im));                                      \
        ull partp_[4] = {0ull, 0ull, 0ull, 0ull};                              \
        _Pragma("unroll")                                                      \
        for (int k = 0; k < 4; k++) {                                          \
            ull x_ = fma2(rpk_, w1ap[k], b1p[k]);                              \
            x_ = fma2(ipk_, w1bp[k], x_);                                      \
            hid[k] = silu2(x_, halfpk);                                        \
            _Pragma("unroll")                                                  \
            for (int h = 0; h < 4; h++)                                        \
                partp_[h] = fma2(u4p[h][k], hid[k], partp_[h]);                \
        }                                                                      \
        _Pragma("unroll")                                                      \
        for (int h = 0; h < 4; h++) { float a_, b_; upk2(a_, b_, partp_[h]); sc[h] = a_ + b_; } \
    }

    // butterfly over the 8 group lanes (group-scoped mask)
    #define REDUCE8(sc)                                                        \
        _Pragma("unroll")                                                      \
        for (int off = 1; off < 8; off <<= 1) {                                \
            _Pragma("unroll")                                                  \
            for (int h = 0; h < 4; h++)                                        \
                sc[h] += __shfl_xor_sync(gmask, sc[h], off);                   \
        }

    // online-softmax update: fast path branch-free; single rare rescale branch
    #define PROC(sc, hid)                                                      \
    {                                                                          \
        _Pragma("unroll")                                                      \
        for (int h = 0; h < 4; h++) sc[h] += c4[h];                            \
        if (sc[0] > m4[0] || sc[1] > m4[1] || sc[2] > m4[2] || sc[3] > m4[3]) {\
            _Pragma("unroll")                                                  \
            for (int h = 0; h < 4; h++) {                                      \
                if (sc[h] > m4[h]) {                                           \
                    const float corr_ = __expf(m4[h] - sc[h]);                 \
                    m4[h] = sc[h];                                             \
                    s4[h] *= corr_;                                            \
                    const ull cpk_ = pk2(corr_, corr_);                        \
                    _Pragma("unroll")                                          \
                    for (int k = 0; k < 4; k++) accp[h][k] = mul2(accp[h][k], cpk_); \
                }                                                              \
            }                                                                  \
        }                                                                      \
        _Pragma("unroll")                                                      \
        for (int h = 0; h < 4; h++) {                                          \
            const float w_ = __expf(sc[h] - m4[h]);                            \
            s4[h] += w_;                                                       \
            const ull wpk_ = pk2(w_, w_);                                      \
            _Pragma("unroll")                                                  \
            for (int k = 0; k < 4; k++)                                        \
                accp[h][k] = fma2(wpk_, hid[k], accp[h][k]);                   \
        }                                                                      \
    }

    const int gid = blockIdx.x * GPB + (tid >> 3);
    const int stride = 2 * NGROUPS;
    for (int p = 2 * gid; p + 1 < N; p += stride) {
        const float2 rv = *(const float2*)(rr + p);
        const float2 iv = *(const float2*)(ri + p);

        ull hidA[4], hidB[4];
        float scA[4], scB[4];
        HIDSCORE(rv.x, iv.x, hidA, scA)
        HIDSCORE(rv.y, iv.y, hidB, scB)
        REDUCE8(scA)
        REDUCE8(scB)
        PROC(scA, hidA)
        PROC(scB, hidB)
    }
    // odd-N tail (never taken for N = 1M; kept for safety, group-uniform)
    {
        int p = 2 * gid;
        while (p + 1 < N) p += stride;
        if (p < N) {
            const float r = rr[p], im = ri[p];
            ull hidA[4]; float scA[4];
            HIDSCORE(r, im, hidA, scA)
            REDUCE8(scA)
            PROC(scA, hidA)
        }
    }

    // ---- combine 4 groups of this warp (xor 8, 16); warp reconverged -------
    #pragma unroll
    for (int off = 8; off <= 16; off <<= 1) {
        #pragma unroll
        for (int h = 0; h < 4; h++) {
            const float om = __shfl_xor_sync(0xffffffffu, m4[h], off);
            const float os = __shfl_xor_sync(0xffffffffu, s4[h], off);
            const float nm = fmaxf(m4[h], om);
            const float c1 = __expf(m4[h] - nm);
            const float c2 = __expf(om - nm);
            s4[h] = s4[h] * c1 + os * c2;
            const ull c1p = pk2(c1, c1), c2p = pk2(c2, c2);
            #pragma unroll
            for (int k = 0; k < 4; k++) {
                const ull oa = __shfl_xor_sync(0xffffffffu, accp[h][k], off);
                accp[h][k] = fma2(accp[h][k], c1p, mul2(oa, c2p));
            }
            m4[h] = nm;
        }
    }

    // ---- block combine via shared (NWARP warps) ------------------------------
    const int wid = tid >> 5;
    if (lane < 8) {
        #pragma unroll
        for (int h = 0; h < 4; h++) {
            #pragma unroll
            for (int k = 0; k < 4; k++) {
                float a, b; upk2(a, b, accp[h][k]);
                sh_acc[wid][h][lane * 8 + 2 * k]     = a;
                sh_acc[wid][h][lane * 8 + 2 * k + 1] = b;
            }
            if (lane == 0) { sh_m[wid][h] = m4[h]; sh_s[wid][h] = s4[h]; }
        }
    }
    __syncthreads();

    if (tid < 256) {
        const int h = tid >> 6;
        const int j = tid & 63;
        float M = -1e30f;
        #pragma unroll
        for (int w = 0; w < NWARP; w++) M = fmaxf(M, sh_m[w][h]);
        float A = 0.f, S = 0.f;
        #pragma unroll
        for (int w = 0; w < NWARP; w++) {
            const float e = __expf(sh_m[w][h] - M);
            A = fmaf(e, sh_acc[w][h][j], A);
            S = fmaf(e, sh_s[w][h], S);
        }
        g_part[blockIdx.x][h][2 + j] = A;
        if (j == 0) { g_part[blockIdx.x][h][0] = M; g_part[blockIdx.x][h][1] = S; }
    }
}

// -----------------------------------------------------------------------------
// Final: combine per-block partials (parallelized, high-MLP), apply W2/b2,
// Wv/bv, out_proj.  1 block, 256 threads.
// -----------------------------------------------------------------------------
__global__ void final_kernel(const float* __restrict__ W2,
                             const float* __restrict__ b2,
                             const float* __restrict__ ipw,
                             const float* __restrict__ ipb,
                             const float* __restrict__ opw,
                             const float* __restrict__ opb,
                             float* __restrict__ out)
{
    __shared__ float sh_mx[4];
    __shared__ float sh_e[NB][4];
    __shared__ float sh_S[4];
    __shared__ float sh_p[4][64];
    __shared__ float sh_hbar[4][64];
    __shared__ float sh_pooled[64];
    const int t = threadIdx.x;
    const int h = t >> 6;
    const int j = t & 63;

    // load all per-block maxima in parallel (592 loads over 256 threads)
    for (int idx = t; idx < NB * 4; idx += 256) {
        const int b = idx >> 2, hh = idx & 3;
        sh_e[b][hh] = g_part[b][hh][0];
    }
    __syncthreads();
    if (t < 4) {
        float M = -1e30f;
        #pragma unroll 4
        for (int b = 0; b < NB; b++) M = fmaxf(M, sh_e[b][t]);
        sh_mx[t] = M;
    }
    __syncthreads();
    for (int idx = t; idx < NB * 4; idx += 256) {
        const int b = idx >> 2, hh = idx & 3;
        sh_e[b][hh] = __expf(sh_e[b][hh] - sh_mx[hh]);
    }
    __syncthreads();

    // S (4 threads) concurrent with A (all 256 threads)
    if (t >= 252) {
        const int hh = t - 252;
        float S = 0.f;
        #pragma unroll 4
        for (int b = 0; b < NB; b++) S = fmaf(sh_e[b][hh], __ldg(&g_part[b][hh][1]), S);
        sh_S[hh] = S;
    }
    float A = 0.f;
    #pragma unroll 4
    for (int b = 0; b < NB; b++)
        A = fmaf(sh_e[b][h], __ldg(&g_part[b][h][2 + j]), A);
    __syncthreads();
    sh_p[h][j] = A / sh_S[h];     // E[hidden] under attn, head h
    __syncthreads();

    float hb = b2[j];
    #pragma unroll 8
    for (int m = 0; m < 64; m++) hb = fmaf(W2[j * 64 + m], sh_p[h][m], hb);
    sh_hbar[h][j] = hb;
    __syncthreads();

    if (t < 64) {
        const int e = t, hh = t >> 4;
        float pl = ipb[128 + e];
        #pragma unroll 8
        for (int jj = 0; jj < 64; jj++)
            pl = fmaf(ipw[(128 + e) * 64 + jj], sh_hbar[hh][jj], pl);
        sh_pooled[e] = pl;
    }
    __syncthreads();

    if (t < 64) {
        float o = opb[t];
        #pragma unroll 8
        for (int e = 0; e < 64; e++) o = fmaf(opw[t * 64 + e], sh_pooled[e], o);
        out[t] = o;
    }
}

// -----------------------------------------------------------------------------
extern "C" void kernel_launch(void* const* d_in, const int* in_sizes, int n_in,
                              void* d_out, int out_size)
{
    const float* rr    = (const float*)d_in[0];   // rho_real (1024*1024)
    const float* ri    = (const float*)d_in[1];   // rho_imag
    // d_in[2..5]: l_A, l_B, Z_A, Z_B — unused by the reference math
    const float* W1    = (const float*)d_in[6];   // (64,2)
    const float* b1    = (const float*)d_in[7];   // (64)
    const float* W2    = (const float*)d_in[8];   // (64,64)
    const float* b2    = (const float*)d_in[9];   // (64)
    const float* query = (const float*)d_in[10];  // (1,64)
    const float* ipw   = (const float*)d_in[11];  // (192,64)
    const float* ipb   = (const float*)d_in[12];  // (192)
    const float* opw   = (const float*)d_in[13];  // (64,64)
    const float* opb   = (const float*)d_in[14];  // (64)
    const int N = in_sizes[0];

    main_kernel<<<NB, NTHR>>>(rr, ri, W1, b1, W2, b2, query, ipw, ipb, N);
    final_kernel<<<1, 256>>>(W2, b2, ipw, ipb, opw, opb, (float*)d_out);
}

// round 4
// speedup vs baseline: 1.8811x; 1.8811x over previous
#include <cuda_runtime.h>
#include <math.h>

#define NB      148              // one block per SM, single wave
#define NTHR    384              // 12 warps, ~170 regs/thread
#define GPB     (NTHR / 8)       // 48 groups per block
#define NGROUPS (NB * GPB)       // 7104
#define NWARP   (NTHR / 32)      // 12

typedef unsigned long long ull;

// Per-block partials: [block][head][ s, acc[64] ]  (fixed softmax base = 0)
__device__ float g_part[NB][4][65];
__device__ unsigned g_done = 0;

// ---- packed f32x2 helpers (ptxas never auto-fuses FFMA2) --------------------
__device__ __forceinline__ ull pk2(float lo, float hi) {
    ull r; asm("mov.b64 %0,{%1,%2};" : "=l"(r) : "f"(lo), "f"(hi)); return r;
}
__device__ __forceinline__ void upk2(float& lo, float& hi, ull p) {
    asm("mov.b64 {%0,%1},%2;" : "=f"(lo), "=f"(hi) : "l"(p));
}
__device__ __forceinline__ ull fma2(ull a, ull b, ull c) {
    ull d; asm("fma.rn.f32x2 %0,%1,%2,%3;" : "=l"(d) : "l"(a), "l"(b), "l"(c)); return d;
}
__device__ __forceinline__ ull mul2(ull a, ull b) {
    ull d; asm("mul.rn.f32x2 %0,%1,%2;" : "=l"(d) : "l"(a), "l"(b)); return d;
}
__device__ __forceinline__ float tanh_ap(float x) {
    float y; asm("tanh.approx.f32 %0,%1;" : "=f"(y) : "f"(x)); return y;
}
__device__ __forceinline__ float ex2_ap(float x) {
    float y; asm("ex2.approx.f32 %0,%1;" : "=f"(y) : "f"(x)); return y;
}
// silu(x) = h + h*tanh(h), h = x/2  -> 1 MUFU per element
__device__ __forceinline__ ull silu2(ull xpk, ull halfpk) {
    ull hpk = mul2(xpk, halfpk);
    float h0, h1; upk2(h0, h1, hpk);
    ull tpk = pk2(tanh_ap(h0), tanh_ap(h1));
    return fma2(hpk, tpk, hpk);
}

// -----------------------------------------------------------------------------
// Single fused kernel: inline prep -> branch-free streaming exp-accumulate ->
// block partial -> last block combines + output projections.
// -----------------------------------------------------------------------------
__global__ void __launch_bounds__(NTHR, 1)
main_kernel(const float* __restrict__ rr,
            const float* __restrict__ ri,
            const float* __restrict__ W1,
            const float* __restrict__ b1,
            const float* __restrict__ W2,
            const float* __restrict__ b2,
            const float* __restrict__ query,
            const float* __restrict__ ipw,   // in_proj_w (192,64)
            const float* __restrict__ ipb,   // in_proj_b (192)
            const float* __restrict__ opw,   // out_proj_w (64,64)
            const float* __restrict__ opb,   // out_proj_b (64)
            float* __restrict__ out,
            int N)
{
    __shared__ float qv[64];
    __shared__ float tt[4][64];
    __shared__ float sh_u[4][64];
    __shared__ float sh_c[4];
    __shared__ float sh_acc[NWARP][4][64];
    __shared__ float sh_s[NWARP][4];

    const int tid  = threadIdx.x;
    const int lane = tid & 31;
    const int sub  = tid & 7;
    const unsigned gmask = 0xFFu << (lane & 24);

    // scale = 1/sqrt(hd) * log2(e), folded so inner exp is a bare ex2.approx
    const float SC = 0.25f * 1.4426950408889634f;

    // ---- inline prep (every block redundantly; ~25K FMA, L2-resident) ------
    if (tid < 64) {
        float a = ipb[tid], a2 = 0.f;
        #pragma unroll 8
        for (int m = 0; m < 64; m += 2) {
            a  = fmaf(query[m],     ipw[tid * 64 + m],     a);
            a2 = fmaf(query[m + 1], ipw[tid * 64 + m + 1], a2);
        }
        qv[tid] = a + a2;
    }
    __syncthreads();
    if (tid < 256) {
        const int h = tid >> 6, j = tid & 63;
        float t = 0.f;
        #pragma unroll 8
        for (int d = 0; d < 16; d++)
            t = fmaf(qv[h * 16 + d], ipw[(64 + h * 16 + d) * 64 + j], t);
        tt[h][j] = t;
    }
    __syncthreads();
    if (tid < 256) {
        const int h = tid >> 6, j = tid & 63;
        float u = 0.f, u2 = 0.f;
        #pragma unroll 8
        for (int jj = 0; jj < 64; jj += 2) {
            u  = fmaf(tt[h][jj],     W2[jj * 64 + j],       u);
            u2 = fmaf(tt[h][jj + 1], W2[(jj + 1) * 64 + j], u2);
        }
        sh_u[h][j] = SC * (u + u2);
    } else if (tid < 260) {
        const int h = tid - 256;
        float c = 0.f;
        for (int d = 0; d < 16; d++) c = fmaf(qv[h * 16 + d], ipb[64 + h * 16 + d], c);
        for (int jj = 0; jj < 64; jj++) c = fmaf(tt[h][jj], b2[jj], c);
        sh_c[h] = SC * c;
    }
    __syncthreads();

    // ---- per-lane packed constants ------------------------------------------
    const int j0 = sub * 8;
    ull w1ap[4], w1bp[4], b1p[4], u4p[4][4];
    #pragma unroll
    for (int k = 0; k < 4; k++) {
        const int j = j0 + 2 * k;
        w1ap[k] = pk2(W1[2 * j],     W1[2 * j + 2]);
        w1bp[k] = pk2(W1[2 * j + 1], W1[2 * j + 3]);
        b1p[k]  = pk2(b1[j], b1[j + 1]);
        #pragma unroll
        for (int h = 0; h < 4; h++) u4p[h][k] = pk2(sh_u[h][j], sh_u[h][j + 1]);
    }
    float c4[4];
    #pragma unroll
    for (int h = 0; h < 4; h++) c4[h] = sh_c[h];
    const ull halfpk = pk2(0.5f, 0.5f);

    // ---- accumulators (fixed base: w = 2^(sc'), softmax shift-invariant) -----
    float s4[4] = {0.f, 0.f, 0.f, 0.f};
    ull accp[4][4];
    #pragma unroll
    for (int h = 0; h < 4; h++)
        #pragma unroll
        for (int k = 0; k < 4; k++) accp[h][k] = 0ull;

    // ---- branch-free streaming loop ------------------------------------------
    const int gid = blockIdx.x * GPB + (tid >> 3);
    for (int p = gid; p < N; p += NGROUPS) {
        const float r  = __ldg(rr + p);
        const float im = __ldg(ri + p);
        const ull rpk = pk2(r, r);
        const ull ipk = pk2(im, im);

        ull hid[4];
        ull partp[4] = {0ull, 0ull, 0ull, 0ull};
        #pragma unroll
        for (int k = 0; k < 4; k++) {
            ull x = fma2(rpk, w1ap[k], b1p[k]);
            x = fma2(ipk, w1bp[k], x);
            hid[k] = silu2(x, halfpk);
            #pragma unroll
            for (int h = 0; h < 4; h++)
                partp[h] = fma2(u4p[h][k], hid[k], partp[h]);
        }
        float sc[4];
        #pragma unroll
        for (int h = 0; h < 4; h++) { float a, b; upk2(a, b, partp[h]); sc[h] = a + b; }

        // butterfly over the 8 group lanes (group-scoped mask: trip counts
        // differ by 1 across groups in the same warp)
        #pragma unroll
        for (int off = 1; off < 8; off <<= 1) {
            #pragma unroll
            for (int h = 0; h < 4; h++)
                sc[h] += __shfl_xor_sync(gmask, sc[h], off);
        }

        #pragma unroll
        for (int h = 0; h < 4; h++) {
            const float w = ex2_ap(sc[h] + c4[h]);   // exp(score/sqrt(hd))
            s4[h] += w;
            const ull wpk = pk2(w, w);
            #pragma unroll
            for (int k = 0; k < 4; k++)
                accp[h][k] = fma2(wpk, hid[k], accp[h][k]);
        }
    }

    // ---- combine 4 groups of this warp (plain sums now) ----------------------
    #pragma unroll
    for (int off = 8; off <= 16; off <<= 1) {
        #pragma unroll
        for (int h = 0; h < 4; h++) {
            s4[h] += __shfl_xor_sync(0xffffffffu, s4[h], off);
            #pragma unroll
            for (int k = 0; k < 4; k++) {
                float a, b; upk2(a, b, accp[h][k]);
                a += __shfl_xor_sync(0xffffffffu, a, off);
                b += __shfl_xor_sync(0xffffffffu, b, off);
                accp[h][k] = pk2(a, b);
            }
        }
    }

    // ---- block combine via shared --------------------------------------------
    const int wid = tid >> 5;
    if (lane < 8) {
        #pragma unroll
        for (int h = 0; h < 4; h++) {
            #pragma unroll
            for (int k = 0; k < 4; k++) {
                float a, b; upk2(a, b, accp[h][k]);
                sh_acc[wid][h][lane * 8 + 2 * k]     = a;
                sh_acc[wid][h][lane * 8 + 2 * k + 1] = b;
            }
            if (lane == 0) sh_s[wid][h] = s4[h];
        }
    }
    __syncthreads();

    if (tid < 256) {
        const int h = tid >> 6;
        const int j = tid & 63;
        float A = 0.f;
        #pragma unroll
        for (int w = 0; w < NWARP; w++) A += sh_acc[w][h][j];
        g_part[blockIdx.x][h][1 + j] = A;
        if (j == 0) {
            float S = 0.f;
            #pragma unroll
            for (int w = 0; w < NWARP; w++) S += sh_s[w][h];
            g_part[blockIdx.x][h][0] = S;
        }
    }

    // ---- last block does the final combine + projections ---------------------
    __threadfence();
    __shared__ bool is_last;
    __shared__ float sh_p[4][64];
    __shared__ float sh_hbar[4][64];
    __shared__ float sh_pooled[64];
    __shared__ float sh_S[4];
    if (tid == 0) is_last = (atomicAdd(&g_done, 1) == NB - 1);
    __syncthreads();
    if (!is_last) return;
    if (tid == 0) g_done = 0;            // reset for next graph replay

    const int h = (tid >> 6) & 3;
    const int j = tid & 63;

    if (tid < 256) {
        float A = 0.f;
        #pragma unroll 4
        for (int b = 0; b < NB; b++) A += __ldg(&g_part[b][h][1 + j]);
        sh_hbar[h][j] = A;               // staging: raw acc sum
    } else if (tid < 260) {
        const int hh = tid - 256;
        float S = 0.f;
        #pragma unroll 4
        for (int b = 0; b < NB; b++) S += __ldg(&g_part[b][hh][0]);
        sh_S[hh] = S;
    }
    __syncthreads();
    if (tid < 256) sh_p[h][j] = sh_hbar[h][j] / sh_S[h];   // E[hidden] head h
    __syncthreads();

    if (tid < 256) {
        float hb = b2[j];
        #pragma unroll 8
        for (int m = 0; m < 64; m++) hb = fmaf(W2[j * 64 + m], sh_p[h][m], hb);
        sh_hbar[h][j] = hb;
    }
    __syncthreads();

    if (tid < 64) {
        const int e = tid, hh = tid >> 4;
        float pl = ipb[128 + e];
        #pragma unroll 8
        for (int jj = 0; jj < 64; jj++)
            pl = fmaf(ipw[(128 + e) * 64 + jj], sh_hbar[hh][jj], pl);
        sh_pooled[e] = pl;
    }
    __syncthreads();

    if (tid < 64) {
        float o = opb[tid];
        #pragma unroll 8
        for (int e = 0; e < 64; e++) o = fmaf(opw[tid * 64 + e], sh_pooled[e], o);
        out[tid] = o;
    }
}

// -----------------------------------------------------------------------------
extern "C" void kernel_launch(void* const* d_in, const int* in_sizes, int n_in,
                              void* d_out, int out_size)
{
    const float* rr    = (const float*)d_in[0];   // rho_real (1024*1024)
    const float* ri    = (const float*)d_in[1];   // rho_imag
    // d_in[2..5]: l_A, l_B, Z_A, Z_B — unused by the reference math
    const float* W1    = (const float*)d_in[6];   // (64,2)
    const float* b1    = (const float*)d_in[7];   // (64)
    const float* W2    = (const float*)d_in[8];   // (64,64)
    const float* b2    = (const float*)d_in[9];   // (64)
    const float* query = (const float*)d_in[10];  // (1,64)
    const float* ipw   = (const float*)d_in[11];  // (192,64)
    const float* ipb   = (const float*)d_in[12];  // (192)
    const float* opw   = (const float*)d_in[13];  // (64,64)
    const float* opb   = (const float*)d_in[14];  // (64)
    const int N = in_sizes[0];

    main_kernel<<<NB, NTHR>>>(rr, ri, W1, b1, W2, b2, query, ipw, ipb,
                              opw, opb, (float*)d_out, N);
}

// round 5
// speedup vs baseline: 2.0737x; 1.1023x over previous
#include <cuda_runtime.h>
#include <math.h>

#define NB      148              // one block per SM, single wave
#define NTHR    384              // 12 warps, 170 regs/thread budget
#define GPB     (NTHR / 8)       // 48 groups per block
#define NGROUPS (NB * GPB)       // 7104
#define NWARP   (NTHR / 32)      // 12

typedef unsigned long long ull;

// Per-block partials: [block][head][ s, acc[64] ]  (fixed softmax base = 0)
__device__ float g_part[NB][4][65];
__device__ unsigned g_done = 0;

// ---- packed f32x2 helpers (ptxas never auto-fuses FFMA2) --------------------
__device__ __forceinline__ ull pk2(float lo, float hi) {
    ull r; asm("mov.b64 %0,{%1,%2};" : "=l"(r) : "f"(lo), "f"(hi)); return r;
}
__device__ __forceinline__ void upk2(float& lo, float& hi, ull p) {
    asm("mov.b64 {%0,%1},%2;" : "=f"(lo), "=f"(hi) : "l"(p));
}
__device__ __forceinline__ ull fma2(ull a, ull b, ull c) {
    ull d; asm("fma.rn.f32x2 %0,%1,%2,%3;" : "=l"(d) : "l"(a), "l"(b), "l"(c)); return d;
}
__device__ __forceinline__ ull mul2(ull a, ull b) {
    ull d; asm("mul.rn.f32x2 %0,%1,%2;" : "=l"(d) : "l"(a), "l"(b)); return d;
}
__device__ __forceinline__ float tanh_ap(float x) {
    float y; asm("tanh.approx.f32 %0,%1;" : "=f"(y) : "f"(x)); return y;
}
__device__ __forceinline__ float ex2_ap(float x) {
    float y; asm("ex2.approx.f32 %0,%1;" : "=f"(y) : "f"(x)); return y;
}
// silu(x) = h + h*tanh(h), h = x/2  -> 1 MUFU per element
__device__ __forceinline__ ull silu2(ull xpk, ull halfpk) {
    ull hpk = mul2(xpk, halfpk);
    float h0, h1; upk2(h0, h1, hpk);
    ull tpk = pk2(tanh_ap(h0), tanh_ap(h1));
    return fma2(hpk, tpk, hpk);
}

// -----------------------------------------------------------------------------
// Single fused kernel: inline prep -> branch-free streaming exp-accumulate
// (2 points per group-iter, prefetched) -> block partial -> last block final.
// -----------------------------------------------------------------------------
__global__ void __launch_bounds__(NTHR, 1)
main_kernel(const float* __restrict__ rr,
            const float* __restrict__ ri,
            const float* __restrict__ W1,
            const float* __restrict__ b1,
            const float* __restrict__ W2,
            const float* __restrict__ b2,
            const float* __restrict__ query,
            const float* __restrict__ ipw,   // in_proj_w (192,64)
            const float* __restrict__ ipb,   // in_proj_b (192)
            const float* __restrict__ opw,   // out_proj_w (64,64)
            const float* __restrict__ opb,   // out_proj_b (64)
            float* __restrict__ out,
            int N)
{
    __shared__ float qv[64];
    __shared__ float tt[4][64];
    __shared__ float sh_u[4][64];
    __shared__ float sh_c[4];
    __shared__ float sh_acc[NWARP][4][64];
    __shared__ float sh_s[NWARP][4];

    const int tid  = threadIdx.x;
    const int lane = tid & 31;
    const int sub  = tid & 7;
    const unsigned gmask = 0xFFu << (lane & 24);

    // scale = 1/sqrt(hd) * log2(e), folded so inner exp is a bare ex2.approx
    const float SC = 0.25f * 1.4426950408889634f;

    // ---- inline prep (every block redundantly; ~25K FMA, L2-resident) ------
    if (tid < 64) {
        float a = ipb[tid], a2 = 0.f;
        #pragma unroll 8
        for (int m = 0; m < 64; m += 2) {
            a  = fmaf(query[m],     ipw[tid * 64 + m],     a);
            a2 = fmaf(query[m + 1], ipw[tid * 64 + m + 1], a2);
        }
        qv[tid] = a + a2;
    }
    __syncthreads();
    if (tid < 256) {
        const int h = tid >> 6, j = tid & 63;
        float t = 0.f;
        #pragma unroll 8
        for (int d = 0; d < 16; d++)
            t = fmaf(qv[h * 16 + d], ipw[(64 + h * 16 + d) * 64 + j], t);
        tt[h][j] = t;
    }
    __syncthreads();
    if (tid < 256) {
        const int h = tid >> 6, j = tid & 63;
        float u = 0.f, u2 = 0.f;
        #pragma unroll 8
        for (int jj = 0; jj < 64; jj += 2) {
            u  = fmaf(tt[h][jj],     W2[jj * 64 + j],       u);
            u2 = fmaf(tt[h][jj + 1], W2[(jj + 1) * 64 + j], u2);
        }
        sh_u[h][j] = SC * (u + u2);
    } else if (tid < 260) {
        const int h = tid - 256;
        float c = 0.f;
        for (int d = 0; d < 16; d++) c = fmaf(qv[h * 16 + d], ipb[64 + h * 16 + d], c);
        for (int jj = 0; jj < 64; jj++) c = fmaf(tt[h][jj], b2[jj], c);
        sh_c[h] = SC * c;
    }
    __syncthreads();

    // ---- per-lane packed constants ------------------------------------------
    const int j0 = sub * 8;
    ull w1ap[4], w1bp[4], b1p[4], u4p[4][4];
    #pragma unroll
    for (int k = 0; k < 4; k++) {
        const int j = j0 + 2 * k;
        w1ap[k] = pk2(W1[2 * j],     W1[2 * j + 2]);
        w1bp[k] = pk2(W1[2 * j + 1], W1[2 * j + 3]);
        b1p[k]  = pk2(b1[j], b1[j + 1]);
        #pragma unroll
        for (int h = 0; h < 4; h++) u4p[h][k] = pk2(sh_u[h][j], sh_u[h][j + 1]);
    }
    float c4[4];
    #pragma unroll
    for (int h = 0; h < 4; h++) c4[h] = sh_c[h];
    const ull halfpk = pk2(0.5f, 0.5f);

    // ---- accumulators (fixed base: w = 2^(sc'), softmax shift-invariant) -----
    float s4[4] = {0.f, 0.f, 0.f, 0.f};
    ull accp[4][4];
    #pragma unroll
    for (int h = 0; h < 4; h++)
        #pragma unroll
        for (int k = 0; k < 4; k++) accp[h][k] = 0ull;

    // hidden + per-head score partial for one point, this lane's 8 dims
    #define HIDSCORE(r, im, hid, sc)                                           \
    {                                                                          \
        const ull rpk_ = pk2((r), (r));                                        \
        const ull ipk_ = pk2((im), (im));                                      \
        ull partp_[4] = {0ull, 0ull, 0ull, 0ull};                              \
        _Pragma("unroll")                                                      \
        for (int k = 0; k < 4; k++) {                                          \
            ull x_ = fma2(rpk_, w1ap[k], b1p[k]);                              \
            x_ = fma2(ipk_, w1bp[k], x_);                                      \
            hid[k] = silu2(x_, halfpk);                                        \
            _Pragma("unroll")                                                  \
            for (int h = 0; h < 4; h++)                                        \
                partp_[h] = fma2(u4p[h][k], hid[k], partp_[h]);                \
        }                                                                      \
        _Pragma("unroll")                                                      \
        for (int h = 0; h < 4; h++) { float a_, b_; upk2(a_, b_, partp_[h]); sc[h] = a_ + b_; } \
    }

    #define REDUCE8(sc)                                                        \
        _Pragma("unroll")                                                      \
        for (int off = 1; off < 8; off <<= 1) {                                \
            _Pragma("unroll")                                                  \
            for (int h = 0; h < 4; h++)                                        \
                sc[h] += __shfl_xor_sync(gmask, sc[h], off);                   \
        }

    #define ACCUM(sc, hid)                                                     \
        _Pragma("unroll")                                                      \
        for (int h = 0; h < 4; h++) {                                          \
            const float w_ = ex2_ap(sc[h] + c4[h]);                            \
            s4[h] += w_;                                                       \
            const ull wpk_ = pk2(w_, w_);                                      \
            _Pragma("unroll")                                                  \
            for (int k = 0; k < 4; k++)                                        \
                accp[h][k] = fma2(wpk_, hid[k], accp[h][k]);                   \
        }

    // ---- branch-free streaming loop: 2 points/iter, prefetched ---------------
    const int gid = blockIdx.x * GPB + (tid >> 3);
    const int Nev = N & ~1;
    const int stride = 2 * NGROUPS;
    int p = 2 * gid;
    if (p < Nev) {
        float2 rv = *(const float2*)(rr + p);
        float2 iv = *(const float2*)(ri + p);
        while (true) {
            const int pn = p + stride;
            const bool more = (pn < Nev);
            const int pc = more ? pn : p;          // clamped prefetch index
            float2 rv_n = *(const float2*)(rr + pc);
            float2 iv_n = *(const float2*)(ri + pc);

            ull hidA[4], hidB[4];
            float scA[4], scB[4];
            HIDSCORE(rv.x, iv.x, hidA, scA)
            HIDSCORE(rv.y, iv.y, hidB, scB)
            REDUCE8(scA)
            REDUCE8(scB)
            ACCUM(scA, hidA)
            ACCUM(scB, hidB)

            if (!more) break;
            p = pn; rv = rv_n; iv = iv_n;
        }
    }
    // odd-N leftover point (group 0 only; group-uniform branch)
    if ((N & 1) && gid == 0) {
        const float r = rr[N - 1], im = ri[N - 1];
        ull hidA[4]; float scA[4];
        HIDSCORE(r, im, hidA, scA)
        REDUCE8(scA)
        ACCUM(scA, hidA)
    }

    // ---- combine 4 groups of this warp (plain sums) ---------------------------
    #pragma unroll
    for (int off = 8; off <= 16; off <<= 1) {
        #pragma unroll
        for (int h = 0; h < 4; h++) {
            s4[h] += __shfl_xor_sync(0xffffffffu, s4[h], off);
            #pragma unroll
            for (int k = 0; k < 4; k++) {
                float a, b; upk2(a, b, accp[h][k]);
                a += __shfl_xor_sync(0xffffffffu, a, off);
                b += __shfl_xor_sync(0xffffffffu, b, off);
                accp[h][k] = pk2(a, b);
            }
        }
    }

    // ---- block combine via shared ---------------------------------------------
    const int wid = tid >> 5;
    if (lane < 8) {
        #pragma unroll
        for (int h = 0; h < 4; h++) {
            #pragma unroll
            for (int k = 0; k < 4; k++) {
                float a, b; upk2(a, b, accp[h][k]);
                sh_acc[wid][h][lane * 8 + 2 * k]     = a;
                sh_acc[wid][h][lane * 8 + 2 * k + 1] = b;
            }
            if (lane == 0) sh_s[wid][h] = s4[h];
        }
    }
    __syncthreads();

    if (tid < 256) {
        const int h = tid >> 6;
        const int j = tid & 63;
        float A = 0.f;
        #pragma unroll
        for (int w = 0; w < NWARP; w++) A += sh_acc[w][h][j];
        g_part[blockIdx.x][h][1 + j] = A;
        if (j == 0) {
            float S = 0.f;
            #pragma unroll
            for (int w = 0; w < NWARP; w++) S += sh_s[w][h];
            g_part[blockIdx.x][h][0] = S;
        }
    }

    // ---- last block does the final combine + projections -----------------------
    __threadfence();
    __shared__ bool is_last;
    __shared__ float sh_p[4][64];
    __shared__ float sh_hbar[4][64];
    __shared__ float sh_pooled[64];
    __shared__ float sh_S[4];
    if (tid == 0) is_last = (atomicAdd(&g_done, 1) == NB - 1);
    __syncthreads();
    if (!is_last) return;
    if (tid == 0) g_done = 0;            // reset for next graph replay

    const int h = (tid >> 6) & 3;
    const int j = tid & 63;

    if (tid < 256) {
        float A = 0.f;
        #pragma unroll 4
        for (int b = 0; b < NB; b++) A += __ldg(&g_part[b][h][1 + j]);
        sh_hbar[h][j] = A;               // staging: raw acc sum
    } else if (tid < 260) {
        const int hh = tid - 256;
        float S = 0.f;
        #pragma unroll 4
        for (int b = 0; b < NB; b++) S += __ldg(&g_part[b][hh][0]);
        sh_S[hh] = S;
    }
    __syncthreads();
    if (tid < 256) sh_p[h][j] = sh_hbar[h][j] / sh_S[h];   // E[hidden] head h
    __syncthreads();

    if (tid < 256) {
        float hb = b2[j];
        #pragma unroll 8
        for (int m = 0; m < 64; m++) hb = fmaf(W2[j * 64 + m], sh_p[h][m], hb);
        sh_hbar[h][j] = hb;
    }
    __syncthreads();

    if (tid < 64) {
        const int e = tid, hh = tid >> 4;
        float pl = ipb[128 + e];
        #pragma unroll 8
        for (int jj = 0; jj < 64; jj++)
            pl = fmaf(ipw[(128 + e) * 64 + jj], sh_hbar[hh][jj], pl);
        sh_pooled[e] = pl;
    }
    __syncthreads();

    if (tid < 64) {
        float o = opb[tid];
        #pragma unroll 8
        for (int e = 0; e < 64; e++) o = fmaf(opw[tid * 64 + e], sh_pooled[e], o);
        out[tid] = o;
    }
}

// -----------------------------------------------------------------------------
extern "C" void kernel_launch(void* const* d_in, const int* in_sizes, int n_in,
                              void* d_out, int out_size)
{
    const float* rr    = (const float*)d_in[0];   // rho_real (1024*1024)
    const float* ri    = (const float*)d_in[1];   // rho_imag
    // d_in[2..5]: l_A, l_B, Z_A, Z_B — unused by the reference math
    const float* W1    = (const float*)d_in[6];   // (64,2)
    const float* b1    = (const float*)d_in[7];   // (64)
    const float* W2    = (const float*)d_in[8];   // (64,64)
    const float* b2    = (const float*)d_in[9];   // (64)
    const float* query = (const float*)d_in[10];  // (1,64)
    const float* ipw   = (const float*)d_in[11];  // (192,64)
    const float* ipb   = (const float*)d_in[12];  // (192)
    const float* opw   = (const float*)d_in[13];  // (64,64)
    const float* opb   = (const float*)d_in[14];  // (64)
    const int N = in_sizes[0];

    main_kernel<<<NB, NTHR>>>(rr, ri, W1, b1, W2, b2, query, ipw, ipb,
                              opw, opb, (float*)d_out, N);
}